// round 13
// baseline (speedup 1.0000x reference)
#include <cuda_runtime.h>
#include <cuda_fp16.h>
#include <cstdint>

#define T_TOK 4096
#define D_DIM 1024
#define H_DIM 2048
#define E_EXP 8
#define K_TOP 2
#define RMAX (T_TOK * K_TOP)
#define NTILE_MAX 72

// ---------------- device scratch (no allocation allowed) ----------------
__device__ int    g_counts[E_EXP];
__device__ int    g_offsets[E_EXP + 1];
__device__ int    g_tile2e[NTILE_MAX];
__device__ int    g_tilem0[NTILE_MAX];
__device__ int    g_tok[RMAX];
__device__ float  g_gw[RMAX];
__device__ __half g_acth[(size_t)RMAX * H_DIM];
__device__ __half g_xh[(size_t)T_TOK * D_DIM];
__device__ __half g_w1h[(size_t)E_EXP * 2 * H_DIM * D_DIM];
__device__ __half g_w2h[(size_t)E_EXP * D_DIM * H_DIM];

// ---------------- helpers ----------------
__device__ __forceinline__ uint32_t smem_u32(const void* p) {
    uint32_t a;
    asm("{ .reg .u64 t; cvta.to.shared.u64 t, %1; cvt.u32.u64 %0, t; }" : "=r"(a) : "l"(p));
    return a;
}
__device__ __forceinline__ void ldm_x4(uint32_t (&r)[4], uint32_t addr) {
    asm volatile("ldmatrix.sync.aligned.m8n8.x4.shared.b16 {%0,%1,%2,%3}, [%4];"
        : "=r"(r[0]), "=r"(r[1]), "=r"(r[2]), "=r"(r[3]) : "r"(addr));
}
#define CP16(d, s)  asm volatile("cp.async.cg.shared.global [%0], [%1], 16;" :: "r"(d), "l"(s))
#define CPCOMMIT()  asm volatile("cp.async.commit_group;" ::: "memory")
#define CPWAIT1()   asm volatile("cp.async.wait_group 1;" ::: "memory")
#define REDV2(p, v0, v1) \
    asm volatile("red.global.add.v2.f32 [%0], {%1, %2};" :: "l"(p), "f"(v0), "f"(v1) : "memory")

#define MMA16(c, a, b0, b1) \
    asm volatile("mma.sync.aligned.m16n8k16.row.col.f32.f16.f16.f32 " \
        "{%0,%1,%2,%3},{%4,%5,%6,%7},{%8,%9},{%0,%1,%2,%3};" \
        : "+f"((c)[0]), "+f"((c)[1]), "+f"((c)[2]), "+f"((c)[3]) \
        : "r"((a)[0]), "r"((a)[1]), "r"((a)[2]), "r"((a)[3]), "r"(b0), "r"(b1))

#define KC 64                        // K halves per chunk (128 B rows)
#define ASTG (128 * 128)             // 16 KB A per stage
#define BSTG (64 * 128)              // 8 KB B per stage (64 rows)
#define STG  (ASTG + BSTG)           // 24 KB
#define SMEMSZ (3 * STG)             // 72 KB -> 3 CTAs/SM (24 warps/SM)

// ---------------- small kernels ----------------
__global__ void zero_y_kernel(float4* y4, int n4) {
    int i = blockIdx.x * blockDim.x + threadIdx.x;
    if (i < n4) y4[i] = make_float4(0.f, 0.f, 0.f, 0.f);
}
__global__ void f2h_kernel(const float4* __restrict__ src, uint4* __restrict__ dst) {
    int i = blockIdx.x * 256 + threadIdx.x;
    float4 a = src[2 * i], b = src[2 * i + 1];
    __half2 h0 = __floats2half2_rn(a.x, a.y);
    __half2 h1 = __floats2half2_rn(a.z, a.w);
    __half2 h2 = __floats2half2_rn(b.x, b.y);
    __half2 h3 = __floats2half2_rn(b.z, b.w);
    uint4 o;
    o.x = *(uint32_t*)&h0; o.y = *(uint32_t*)&h1;
    o.z = *(uint32_t*)&h2; o.w = *(uint32_t*)&h3;
    dst[i] = o;
}
__global__ void route_fused(const void* __restrict__ idxp, const float* __restrict__ w) {
    __shared__ int cnt[E_EXP], off[E_EXP], cur[E_EXP];
    __shared__ int is64s;
    int t = threadIdx.x;
    if (t < E_EXP) { cnt[t] = 0; cur[t] = 0; }
    if (t == 0) is64s = 1;
    __syncthreads();
    const int* i32 = (const int*)idxp;
    for (int i = t; i < RMAX; i += 1024)
        if ((i & 1) && i32[i] != 0) is64s = 0;
    __syncthreads();
    int is64 = is64s;
    for (int i = t; i < RMAX; i += 1024) {
        int e = is64 ? (int)((const long long*)idxp)[i] : i32[i];
        atomicAdd(&cnt[e], 1);
    }
    __syncthreads();
    if (t == 0) {
        int s = 0, tb = 0;
        for (int e = 0; e < E_EXP; e++) {
            off[e] = s; g_offsets[e] = s; g_counts[e] = cnt[e]; s += cnt[e];
            int nt = (cnt[e] + 127) >> 7;
            for (int i = 0; i < nt; i++) { g_tile2e[tb + i] = e; g_tilem0[tb + i] = i * 128; }
            tb += nt;
        }
        g_offsets[E_EXP] = s;
        for (; tb < NTILE_MAX; tb++) g_tile2e[tb] = -1;
    }
    __syncthreads();
    for (int i = t; i < RMAX; i += 1024) {
        int e = is64 ? (int)((const long long*)idxp)[i] : i32[i];
        int p = atomicAdd(&cur[e], 1);
        int slot = off[e] + p;
        g_tok[slot] = i / K_TOP;
        g_gw[slot]  = w[i];
    }
}

// ---------------- fragments: 8 warps (2M x 4N), warp tile 64(M) x 16(N) ----------------
struct Frag { uint32_t aRow[4]; uint32_t bRow; uint32_t kA[4]; uint32_t kB[4]; };

__device__ __forceinline__ void frag_setup(Frag& f, int lane, int wm, int wn, int off) {
    int lane7 = lane & 7, lg = lane >> 3;
    uint32_t swz = (uint32_t)lane7 << 4;
#pragma unroll
    for (int mi = 0; mi < 4; mi++)
        f.aRow[mi] = (uint32_t)(wm * 64 + mi * 16 + lane7 + ((lg & 1) << 3)) * 128;
    f.bRow = ASTG + (uint32_t)(wn * 16 + lane7 + ((lg >> 1) << 3)) * 128;
#pragma unroll
    for (int ks = 0; ks < 4; ks++) {
        int s = (ks + off) & 3;
        f.kA[ks] = ((uint32_t)(s * 32) + (((uint32_t)lg >> 1) << 4)) ^ swz;
        f.kB[ks] = ((uint32_t)(s * 32) + (((uint32_t)lg & 1) << 4)) ^ swz;
    }
}

__device__ __forceinline__ void ld_frags(uint32_t (&Af)[4][4], uint32_t (&Bq)[4],
                                         const Frag& f, uint32_t Ab, int ks) {
#pragma unroll
    for (int mi = 0; mi < 4; mi++) ldm_x4(Af[mi], Ab + f.aRow[mi] + f.kA[ks]);
    ldm_x4(Bq, Ab + f.bRow + f.kB[ks]);
}
__device__ __forceinline__ void mma_frags(float (&acc)[4][2][4],
                                          uint32_t (&Af)[4][4], uint32_t (&Bq)[4]) {
#pragma unroll
    for (int mi = 0; mi < 4; mi++)
#pragma unroll
        for (int ni = 0; ni < 2; ni++)
            MMA16(acc[mi][ni], Af[mi], Bq[ni * 2], Bq[ni * 2 + 1]);
}

// 3-stage mainloop, r8 schedule
#define MAINLOOP(NC) \
    LOADST(0, 0); CPCOMMIT(); \
    LOADST(1, 1); CPCOMMIT(); \
    { int st = 0, stp = 2; \
      for (int c = 0; c < (NC); c++) { \
        CPWAIT1(); \
        __syncthreads(); \
        uint32_t Ab = sb + st * STG; \
        uint32_t Af[4][4], Bq[4]; \
        ld_frags(Af, Bq, f, Ab, 0); \
        int cn = c + 2; \
        if (cn < (NC)) LOADST(cn, stp); \
        CPCOMMIT(); \
        mma_frags(acc, Af, Bq); \
        _Pragma("unroll") \
        for (int ks = 1; ks < 4; ks++) { \
            ld_frags(Af, Bq, f, Ab, ks); \
            mma_frags(acc, Af, Bq); \
        } \
        st = (st == 2) ? 0 : st + 1; \
        stp = (stp == 2) ? 0 : stp + 1; \
      } }

// ================= fc1: gathered [Me x 1024] x W1^T, fused SwiGLU =================
// Block 128(M) x 64(N = 32 u + 32 gate interleaved per n8 tile); 8 warps 2Mx4N.
__global__ __launch_bounds__(256, 3) void fc1_mma() {
    int til = blockIdx.x;
    int e = g_tile2e[til];
    if (e < 0) return;
    int Me = g_counts[e], m0 = g_tilem0[til], base = g_offsets[e];
    int hb = blockIdx.y * 32;

    extern __shared__ char smem[];
    uint32_t sb = smem_u32(smem);
    int tid = threadIdx.x, lane = tid & 31, wid = tid >> 5;
    int wm = wid & 1, wn = wid >> 1;        // wn in 0..3
    uint32_t qr = lane >> 2, qc = lane & 3;
    int soff = (((wid >> 2) << 1) | (blockIdx.x & 1)) & 3;

    // A loader: 2 threads/row, 4x16B
    int arow = tid >> 1;
    int mrow = m0 + arow; if (mrow > Me - 1) mrow = Me - 1;
    const __half* agp = g_xh + (size_t)g_tok[base + mrow] * D_DIM + (tid & 1) * 32;
    uint32_t adst[4];
#pragma unroll
    for (int j = 0; j < 4; j++) {
        int cc = (tid & 1) * 4 + j;
        adst[j] = arow * 128 + ((cc * 16) ^ ((arow & 7) << 4));
    }
    // B loader: 4 threads/row (64 rows), 2x16B each
    int brow = tid >> 2;
    int q = brow >> 3, r = brow & 7;
    int hrow = hb + (q >> 1) * 8 + r;
    int grow = (q & 1) ? (H_DIM + hrow) : hrow;
    int sc = (tid & 3) * 2;
    const __half* bgp = g_w1h + (size_t)e * 2 * H_DIM * D_DIM + (size_t)grow * D_DIM + sc * 8;
    uint32_t bdst[2];
#pragma unroll
    for (int j = 0; j < 2; j++)
        bdst[j] = ASTG + brow * 128 + (((sc + j) * 16) ^ ((brow & 7) << 4));

#define LOADST(c, st) do { \
        uint32_t so = sb + (st) * STG; \
        const __half* a_ = agp + (c) * KC; \
        const __half* b_ = bgp + (c) * KC; \
        _Pragma("unroll") for (int j = 0; j < 4; j++) CP16(so + adst[j], a_ + j * 8); \
        _Pragma("unroll") for (int j = 0; j < 2; j++) CP16(so + bdst[j], b_ + j * 8); \
    } while (0)

    float acc[4][2][4];
#pragma unroll
    for (int i = 0; i < 4; i++)
#pragma unroll
        for (int j = 0; j < 2; j++)
#pragma unroll
            for (int k = 0; k < 4; k++) acc[i][j][k] = 0.f;

    Frag f; frag_setup(f, lane, wm, wn, soff);

    MAINLOOP(D_DIM / KC)   // 16 chunks
#undef LOADST

    // epilogue: warp covers n = wn*16..+15 -> u tile (acc[.][0]) + gate tile (acc[.][1]),
    // both mapping to h-cols hb + wn*8 + qc*2
#pragma unroll
    for (int mi = 0; mi < 4; mi++) {
        int r0 = m0 + wm * 64 + mi * 16 + (int)qr;
        int r1 = r0 + 8;
        float* u = acc[mi][0];
        float* g = acc[mi][1];
        int hcol = hb + wn * 8 + (int)qc * 2;
        if (r0 < Me) {
            float g0 = g[0], g1 = g[1];
            float v0 = u[0] * (g0 / (1.f + __expf(-g0)));
            float v1 = u[1] * (g1 / (1.f + __expf(-g1)));
            *(__half2*)(g_acth + (size_t)(base + r0) * H_DIM + hcol) = __floats2half2_rn(v0, v1);
        }
        if (r1 < Me) {
            float g2 = g[2], g3 = g[3];
            float v2 = u[2] * (g2 / (1.f + __expf(-g2)));
            float v3 = u[3] * (g3 / (1.f + __expf(-g3)));
            *(__half2*)(g_acth + (size_t)(base + r1) * H_DIM + hcol) = __floats2half2_rn(v2, v3);
        }
    }
}

// ================= fc2: [Me x 2048] x W2^T, split-K=2, weighted scatter-add =================
__global__ __launch_bounds__(256, 3) void fc2_mma(float* __restrict__ y) {
    int til = blockIdx.x;
    int e = g_tile2e[til];
    if (e < 0) return;
    int Me = g_counts[e], m0 = g_tilem0[til], base = g_offsets[e];
    int n0 = blockIdx.y * 64;
    int k0 = blockIdx.z * (H_DIM / 2);

    extern __shared__ char smem[];
    uint32_t sb = smem_u32(smem);
    int tid = threadIdx.x, lane = tid & 31, wid = tid >> 5;
    int wm = wid & 1, wn = wid >> 1;
    uint32_t qr = lane >> 2, qc = lane & 3;
    int soff = (((wid >> 2) << 1) | (blockIdx.x & 1)) & 3;

    int arow = tid >> 1;
    int mrow = m0 + arow; if (mrow > Me - 1) mrow = Me - 1;
    const __half* agp = g_acth + (size_t)(base + mrow) * H_DIM + k0 + (tid & 1) * 32;
    uint32_t adst[4];
#pragma unroll
    for (int j = 0; j < 4; j++) {
        int cc = (tid & 1) * 4 + j;
        adst[j] = arow * 128 + ((cc * 16) ^ ((arow & 7) << 4));
    }
    int brow = tid >> 2;
    int sc = (tid & 3) * 2;
    const __half* bgp = g_w2h + (size_t)e * D_DIM * H_DIM + (size_t)(n0 + brow) * H_DIM + k0 + sc * 8;
    uint32_t bdst[2];
#pragma unroll
    for (int j = 0; j < 2; j++)
        bdst[j] = ASTG + brow * 128 + (((sc + j) * 16) ^ ((brow & 7) << 4));

#define LOADST(c, st) do { \
        uint32_t so = sb + (st) * STG; \
        const __half* a_ = agp + (c) * KC; \
        const __half* b_ = bgp + (c) * KC; \
        _Pragma("unroll") for (int j = 0; j < 4; j++) CP16(so + adst[j], a_ + j * 8); \
        _Pragma("unroll") for (int j = 0; j < 2; j++) CP16(so + bdst[j], b_ + j * 8); \
    } while (0)

    float acc[4][2][4];
#pragma unroll
    for (int i = 0; i < 4; i++)
#pragma unroll
        for (int j = 0; j < 2; j++)
#pragma unroll
            for (int k = 0; k < 4; k++) acc[i][j][k] = 0.f;

    Frag f; frag_setup(f, lane, wm, wn, soff);

    MAINLOOP(H_DIM / 2 / KC)   // 16 chunks per K-half
#undef LOADST

#pragma unroll
    for (int mi = 0; mi < 4; mi++) {
        int r0 = m0 + wm * 64 + mi * 16 + (int)qr;
        int r1 = r0 + 8;
        int   t0 = 0, t1 = 0;
        float w0 = 0.f, w1 = 0.f;
        bool v0 = (r0 < Me), v1 = (r1 < Me);
        if (v0) { t0 = g_tok[base + r0]; w0 = g_gw[base + r0]; }
        if (v1) { t1 = g_tok[base + r1]; w1 = g_gw[base + r1]; }
#pragma unroll
        for (int ni = 0; ni < 2; ni++) {
            int col = n0 + wn * 16 + ni * 8 + (int)qc * 2;
            float* c = acc[mi][ni];
            if (v0) REDV2(y + (size_t)t0 * D_DIM + col, c[0] * w0, c[1] * w0);
            if (v1) REDV2(y + (size_t)t1 * D_DIM + col, c[2] * w1, c[3] * w1);
        }
    }
}

// ---------------- launch ----------------
extern "C" void kernel_launch(void* const* d_in, const int* in_sizes, int n_in,
                              void* d_out, int out_size) {
    const float* x   = (const float*)d_in[0];
    const float* w   = (const float*)d_in[1];
    const void*  idx = d_in[2];
    const float* W1  = (const float*)d_in[3];
    const float* W2  = (const float*)d_in[4];
    float* y = (float*)d_out;

    cudaFuncSetAttribute(fc1_mma, cudaFuncAttributeMaxDynamicSharedMemorySize, SMEMSZ);
    cudaFuncSetAttribute(fc2_mma, cudaFuncAttributeMaxDynamicSharedMemorySize, SMEMSZ);

    void* xh_p;  cudaGetSymbolAddress(&xh_p,  g_xh);
    void* w1h_p; cudaGetSymbolAddress(&w1h_p, g_w1h);
    void* w2h_p; cudaGetSymbolAddress(&w2h_p, g_w2h);

    // fc1_mma is 0-based launch #3 -> lands in ncu's -s 5 window
    f2h_kernel<<<T_TOK * D_DIM / 8 / 256, 256>>>((const float4*)x, (uint4*)xh_p);    // 0
    f2h_kernel<<<(size_t)E_EXP * 2 * H_DIM * D_DIM / 8 / 256, 256>>>
        ((const float4*)W1, (uint4*)w1h_p);                                          // 1
    route_fused<<<1, 1024>>>(idx, w);                                                // 2

    dim3 g1(NTILE_MAX, H_DIM / 32, 1);        // (72, 64)
    fc1_mma<<<g1, 256, SMEMSZ>>>();                                                  // 3 <- ncu

    f2h_kernel<<<(size_t)E_EXP * D_DIM * H_DIM / 8 / 256, 256>>>
        ((const float4*)W2, (uint4*)w2h_p);                                          // 4
    int n4 = T_TOK * D_DIM / 4;
    zero_y_kernel<<<(n4 + 255) / 256, 256>>>((float4*)y, n4);                        // 5

    dim3 g2(NTILE_MAX, D_DIM / 64, 2);        // (72, 16, 2)
    fc2_mma<<<g2, 256, SMEMSZ>>>(y);                                                 // 6
}

// round 15
// speedup vs baseline: 1.1462x; 1.1462x over previous
#include <cuda_runtime.h>
#include <cuda_fp16.h>
#include <cstdint>

#define T_TOK 4096
#define D_DIM 1024
#define H_DIM 2048
#define E_EXP 8
#define K_TOP 2
#define RMAX (T_TOK * K_TOP)
#define NTILE_MAX 72

// ---------------- device scratch (no allocation allowed) ----------------
__device__ int    g_counts[E_EXP];
__device__ int    g_offsets[E_EXP + 1];
__device__ int    g_tile2e[NTILE_MAX];
__device__ int    g_tilem0[NTILE_MAX];
__device__ int    g_tok[RMAX];
__device__ float  g_gw[RMAX];
__device__ __half g_acth[(size_t)RMAX * H_DIM];
__device__ __half g_xh[(size_t)T_TOK * D_DIM];
__device__ __half g_w1h[(size_t)E_EXP * 2 * H_DIM * D_DIM];
__device__ __half g_w2h[(size_t)E_EXP * D_DIM * H_DIM];

// ---------------- helpers ----------------
__device__ __forceinline__ uint32_t smem_u32(const void* p) {
    uint32_t a;
    asm("{ .reg .u64 t; cvta.to.shared.u64 t, %1; cvt.u32.u64 %0, t; }" : "=r"(a) : "l"(p));
    return a;
}
__device__ __forceinline__ void ldm_x4(uint32_t (&r)[4], uint32_t addr) {
    asm volatile("ldmatrix.sync.aligned.m8n8.x4.shared.b16 {%0,%1,%2,%3}, [%4];"
        : "=r"(r[0]), "=r"(r[1]), "=r"(r[2]), "=r"(r[3]) : "r"(addr));
}
#define CP16(d, s)  asm volatile("cp.async.cg.shared.global [%0], [%1], 16;" :: "r"(d), "l"(s))
#define CPCOMMIT()  asm volatile("cp.async.commit_group;" ::: "memory")
#define CPWAIT1()   asm volatile("cp.async.wait_group 1;" ::: "memory")
#define REDV2(p, v0, v1) \
    asm volatile("red.global.add.v2.f32 [%0], {%1, %2};" :: "l"(p), "f"(v0), "f"(v1) : "memory")

#define MMA16(c, a, b0, b1) \
    asm volatile("mma.sync.aligned.m16n8k16.row.col.f32.f16.f16.f32 " \
        "{%0,%1,%2,%3},{%4,%5,%6,%7},{%8,%9},{%0,%1,%2,%3};" \
        : "+f"((c)[0]), "+f"((c)[1]), "+f"((c)[2]), "+f"((c)[3]) \
        : "r"((a)[0]), "r"((a)[1]), "r"((a)[2]), "r"((a)[3]), "r"(b0), "r"(b1))

#define KC 64                        // K halves per chunk (128 B rows)
#define ASTG (128 * 128)             // 16 KB A per stage
#define BSTG (128 * 128)             // 16 KB B per stage
#define STG  (ASTG + BSTG)           // 32 KB
#define SMEMSZ (3 * STG)             // 96 KB -> 2 CTAs/SM (16 warps/SM)

// ---------------- small kernels ----------------
__global__ void zero_y_kernel(float4* y4, int n4) {
    int i = blockIdx.x * blockDim.x + threadIdx.x;
    if (i < n4) y4[i] = make_float4(0.f, 0.f, 0.f, 0.f);
}
__global__ void f2h_kernel(const float4* __restrict__ src, uint4* __restrict__ dst) {
    int i = blockIdx.x * 256 + threadIdx.x;
    float4 a = src[2 * i], b = src[2 * i + 1];
    __half2 h0 = __floats2half2_rn(a.x, a.y);
    __half2 h1 = __floats2half2_rn(a.z, a.w);
    __half2 h2 = __floats2half2_rn(b.x, b.y);
    __half2 h3 = __floats2half2_rn(b.z, b.w);
    uint4 o;
    o.x = *(uint32_t*)&h0; o.y = *(uint32_t*)&h1;
    o.z = *(uint32_t*)&h2; o.w = *(uint32_t*)&h3;
    dst[i] = o;
}
__global__ void route_fused(const void* __restrict__ idxp, const float* __restrict__ w) {
    __shared__ int cnt[E_EXP], off[E_EXP], cur[E_EXP];
    __shared__ int is64s;
    int t = threadIdx.x;
    if (t < E_EXP) { cnt[t] = 0; cur[t] = 0; }
    if (t == 0) is64s = 1;
    __syncthreads();
    const int* i32 = (const int*)idxp;
    for (int i = t; i < RMAX; i += 1024)
        if ((i & 1) && i32[i] != 0) is64s = 0;
    __syncthreads();
    int is64 = is64s;
    for (int i = t; i < RMAX; i += 1024) {
        int e = is64 ? (int)((const long long*)idxp)[i] : i32[i];
        atomicAdd(&cnt[e], 1);
    }
    __syncthreads();
    if (t == 0) {
        int s = 0, tb = 0;
        for (int e = 0; e < E_EXP; e++) {
            off[e] = s; g_offsets[e] = s; g_counts[e] = cnt[e]; s += cnt[e];
            int nt = (cnt[e] + 127) >> 7;
            for (int i = 0; i < nt; i++) { g_tile2e[tb + i] = e; g_tilem0[tb + i] = i * 128; }
            tb += nt;
        }
        g_offsets[E_EXP] = s;
        for (; tb < NTILE_MAX; tb++) g_tile2e[tb] = -1;
    }
    __syncthreads();
    for (int i = t; i < RMAX; i += 1024) {
        int e = is64 ? (int)((const long long*)idxp)[i] : i32[i];
        int p = atomicAdd(&cur[e], 1);
        int slot = off[e] + p;
        g_tok[slot] = i / K_TOP;
        g_gw[slot]  = w[i];
    }
}

// ---------------- fragments: warp tile 64(M) x 32(N), staggered slice order ----------------
struct Frag { uint32_t aRow[4]; uint32_t bRow[2]; uint32_t kA[4]; uint32_t kB[4]; };

__device__ __forceinline__ void frag_setup(Frag& f, int lane, int wm, int wn, int off) {
    int lane7 = lane & 7, lg = lane >> 3;
    uint32_t swz = (uint32_t)lane7 << 4;
#pragma unroll
    for (int mi = 0; mi < 4; mi++)
        f.aRow[mi] = (uint32_t)(wm * 64 + mi * 16 + lane7 + ((lg & 1) << 3)) * 128;
#pragma unroll
    for (int nj = 0; nj < 2; nj++)
        f.bRow[nj] = ASTG + (uint32_t)(wn * 32 + nj * 16 + lane7 + ((lg >> 1) << 3)) * 128;
#pragma unroll
    for (int ks = 0; ks < 4; ks++) {
        int s = (ks + off) & 3;
        f.kA[ks] = ((uint32_t)(s * 32) + (((uint32_t)lg >> 1) << 4)) ^ swz;
        f.kB[ks] = ((uint32_t)(s * 32) + (((uint32_t)lg & 1) << 4)) ^ swz;
    }
}

__device__ __forceinline__ void ld_frags(uint32_t (&Af)[4][4], uint32_t (&Bq)[2][4],
                                         const Frag& f, uint32_t Ab, int ks) {
#pragma unroll
    for (int mi = 0; mi < 4; mi++) ldm_x4(Af[mi], Ab + f.aRow[mi] + f.kA[ks]);
#pragma unroll
    for (int nj = 0; nj < 2; nj++) ldm_x4(Bq[nj], Ab + f.bRow[nj] + f.kB[ks]);
}
__device__ __forceinline__ void mma_frags(float (&acc)[4][4][4],
                                          uint32_t (&Af)[4][4], uint32_t (&Bq)[2][4]) {
#pragma unroll
    for (int mi = 0; mi < 4; mi++)
#pragma unroll
        for (int ni = 0; ni < 4; ni++) {
            const uint32_t* bq = Bq[ni >> 1] + ((ni & 1) << 1);
            MMA16(acc[mi][ni], Af[mi], bq[0], bq[1]);
        }
}

#define MAINLOOP(NC) \
    LOADST(0, 0); CPCOMMIT(); \
    LOADST(1, 1); CPCOMMIT(); \
    { int st = 0, stp = 2; \
      for (int c = 0; c < (NC); c++) { \
        CPWAIT1(); \
        __syncthreads(); \
        uint32_t Ab = sb + st * STG; \
        uint32_t Af[4][4], Bq[2][4]; \
        ld_frags(Af, Bq, f, Ab, 0); \
        int cn = c + 2; \
        if (cn < (NC)) LOADST(cn, stp); \
        CPCOMMIT(); \
        mma_frags(acc, Af, Bq); \
        _Pragma("unroll") \
        for (int ks = 1; ks < 4; ks++) { \
            ld_frags(Af, Bq, f, Ab, ks); \
            mma_frags(acc, Af, Bq); \
        } \
        st = (st == 2) ? 0 : st + 1; \
        stp = (stp == 2) ? 0 : stp + 1; \
      } }

// ================= fc1: gathered [Me x 1024] x W1^T, fused SwiGLU =================
__global__ __launch_bounds__(256, 2) void fc1_mma() {
    int til = blockIdx.x;
    int e = g_tile2e[til];
    if (e < 0) return;
    int Me = g_counts[e], m0 = g_tilem0[til], base = g_offsets[e];
    int hb = blockIdx.y * 64;

    extern __shared__ char smem[];
    uint32_t sb = smem_u32(smem);
    int tid = threadIdx.x, lane = tid & 31, wid = tid >> 5;
    int wm = wid & 1, wn = wid >> 1;
    uint32_t qr = lane >> 2, qc = lane & 3;
    int soff = (((wid >> 2) << 1) | (blockIdx.x & 1)) & 3;

    int arow = tid >> 1;
    int mrow = m0 + arow; if (mrow > Me - 1) mrow = Me - 1;
    const __half* agp = g_xh + (size_t)g_tok[base + mrow] * D_DIM + (tid & 1) * 32;
    uint32_t adst[4];
#pragma unroll
    for (int j = 0; j < 4; j++) {
        int cc = (tid & 1) * 4 + j;
        adst[j] = arow * 128 + ((cc * 16) ^ ((arow & 7) << 4));
    }
    int brow = tid >> 1;
    int hrow = hb + ((brow >> 4) << 3) + (brow & 7);
    int grow = ((brow >> 3) & 1) ? (H_DIM + hrow) : hrow;
    const __half* bgp = g_w1h + (size_t)e * 2 * H_DIM * D_DIM + (size_t)grow * D_DIM + (tid & 1) * 32;
    uint32_t bdst[4];
#pragma unroll
    for (int j = 0; j < 4; j++) {
        int cc = (tid & 1) * 4 + j;
        bdst[j] = ASTG + brow * 128 + ((cc * 16) ^ ((brow & 7) << 4));
    }

#define LOADST(c, st) do { \
        uint32_t so = sb + (st) * STG; \
        const __half* a_ = agp + (c) * KC; \
        const __half* b_ = bgp + (c) * KC; \
        _Pragma("unroll") for (int j = 0; j < 4; j++) CP16(so + adst[j], a_ + j * 8); \
        _Pragma("unroll") for (int j = 0; j < 4; j++) CP16(so + bdst[j], b_ + j * 8); \
    } while (0)

    float acc[4][4][4];
#pragma unroll
    for (int i = 0; i < 4; i++)
#pragma unroll
        for (int j = 0; j < 4; j++)
#pragma unroll
            for (int k = 0; k < 4; k++) acc[i][j][k] = 0.f;

    Frag f; frag_setup(f, lane, wm, wn, soff);

    MAINLOOP(D_DIM / KC)   // 16 chunks
#undef LOADST

#pragma unroll
    for (int mi = 0; mi < 4; mi++) {
        int r0 = m0 + wm * 64 + mi * 16 + (int)qr;
        int r1 = r0 + 8;
#pragma unroll
        for (int njp = 0; njp < 2; njp++) {
            float* u = acc[mi][njp * 2];
            float* g = acc[mi][njp * 2 + 1];
            int hcol = hb + (wn * 2 + njp) * 8 + (int)qc * 2;
            if (r0 < Me) {
                float g0 = g[0], g1 = g[1];
                float v0 = u[0] * (g0 / (1.f + __expf(-g0)));
                float v1 = u[1] * (g1 / (1.f + __expf(-g1)));
                *(__half2*)(g_acth + (size_t)(base + r0) * H_DIM + hcol) = __floats2half2_rn(v0, v1);
            }
            if (r1 < Me) {
                float g2 = g[2], g3 = g[3];
                float v2 = u[2] * (g2 / (1.f + __expf(-g2)));
                float v3 = u[3] * (g3 / (1.f + __expf(-g3)));
                *(__half2*)(g_acth + (size_t)(base + r1) * H_DIM + hcol) = __floats2half2_rn(v2, v3);
            }
        }
    }
}

// ================= fc2: [Me x 2048] x W2^T, split-K=2, weighted scatter-add =================
__global__ __launch_bounds__(256, 2) void fc2_mma(float* __restrict__ y) {
    int til = blockIdx.x;
    int e = g_tile2e[til];
    if (e < 0) return;
    int Me = g_counts[e], m0 = g_tilem0[til], base = g_offsets[e];
    int n0 = blockIdx.y * 128;
    int k0 = blockIdx.z * (H_DIM / 2);

    extern __shared__ char smem[];
    uint32_t sb = smem_u32(smem);
    int tid = threadIdx.x, lane = tid & 31, wid = tid >> 5;
    int wm = wid & 1, wn = wid >> 1;
    uint32_t qr = lane >> 2, qc = lane & 3;
    int soff = (((wid >> 2) << 1) | (blockIdx.x & 1)) & 3;

    int arow = tid >> 1;
    int mrow = m0 + arow; if (mrow > Me - 1) mrow = Me - 1;
    const __half* agp = g_acth + (size_t)(base + mrow) * H_DIM + k0 + (tid & 1) * 32;
    uint32_t adst[4];
#pragma unroll
    for (int j = 0; j < 4; j++) {
        int cc = (tid & 1) * 4 + j;
        adst[j] = arow * 128 + ((cc * 16) ^ ((arow & 7) << 4));
    }
    int brow = tid >> 1;
    const __half* bgp = g_w2h + (size_t)e * D_DIM * H_DIM + (size_t)(n0 + brow) * H_DIM + k0 + (tid & 1) * 32;
    uint32_t bdst[4];
#pragma unroll
    for (int j = 0; j < 4; j++) {
        int cc = (tid & 1) * 4 + j;
        bdst[j] = ASTG + brow * 128 + ((cc * 16) ^ ((brow & 7) << 4));
    }

#define LOADST(c, st) do { \
        uint32_t so = sb + (st) * STG; \
        const __half* a_ = agp + (c) * KC; \
        const __half* b_ = bgp + (c) * KC; \
        _Pragma("unroll") for (int j = 0; j < 4; j++) CP16(so + adst[j], a_ + j * 8); \
        _Pragma("unroll") for (int j = 0; j < 4; j++) CP16(so + bdst[j], b_ + j * 8); \
    } while (0)

    float acc[4][4][4];
#pragma unroll
    for (int i = 0; i < 4; i++)
#pragma unroll
        for (int j = 0; j < 4; j++)
#pragma unroll
            for (int k = 0; k < 4; k++) acc[i][j][k] = 0.f;

    Frag f; frag_setup(f, lane, wm, wn, soff);

    MAINLOOP(H_DIM / 2 / KC)   // 16 chunks per K-half
#undef LOADST

#pragma unroll
    for (int mi = 0; mi < 4; mi++) {
        int r0 = m0 + wm * 64 + mi * 16 + (int)qr;
        int r1 = r0 + 8;
        int   t0 = 0, t1 = 0;
        float w0 = 0.f, w1 = 0.f;
        bool v0 = (r0 < Me), v1 = (r1 < Me);
        if (v0) { t0 = g_tok[base + r0]; w0 = g_gw[base + r0]; }
        if (v1) { t1 = g_tok[base + r1]; w1 = g_gw[base + r1]; }
#pragma unroll
        for (int ni = 0; ni < 4; ni++) {
            int col = n0 + wn * 32 + ni * 8 + (int)qc * 2;
            float* c = acc[mi][ni];
            if (v0) REDV2(y + (size_t)t0 * D_DIM + col, c[0] * w0, c[1] * w0);
            if (v1) REDV2(y + (size_t)t1 * D_DIM + col, c[2] * w1, c[3] * w1);
        }
    }
}

// ---------------- launch: fork/join overlap of side work under conversions+fc1 ----------------
extern "C" void kernel_launch(void* const* d_in, const int* in_sizes, int n_in,
                              void* d_out, int out_size) {
    const float* x   = (const float*)d_in[0];
    const float* w   = (const float*)d_in[1];
    const void*  idx = d_in[2];
    const float* W1  = (const float*)d_in[3];
    const float* W2  = (const float*)d_in[4];
    float* y = (float*)d_out;

    static cudaStream_t s1 = nullptr;
    static cudaEvent_t ev_fork = nullptr, ev_route = nullptr, ev_join = nullptr;
    if (s1 == nullptr) {
        cudaStreamCreateWithFlags(&s1, cudaStreamNonBlocking);
        cudaEventCreateWithFlags(&ev_fork,  cudaEventDisableTiming);
        cudaEventCreateWithFlags(&ev_route, cudaEventDisableTiming);
        cudaEventCreateWithFlags(&ev_join,  cudaEventDisableTiming);
        cudaFuncSetAttribute(fc1_mma, cudaFuncAttributeMaxDynamicSharedMemorySize, SMEMSZ);
        cudaFuncSetAttribute(fc2_mma, cudaFuncAttributeMaxDynamicSharedMemorySize, SMEMSZ);
    }

    void* xh_p;  cudaGetSymbolAddress(&xh_p,  g_xh);
    void* w1h_p; cudaGetSymbolAddress(&w1h_p, g_w1h);
    void* w2h_p; cudaGetSymbolAddress(&w2h_p, g_w2h);

    // fork: side stream does route + W2 conversion + zero_y while main stream
    // does the x/W1 conversions that gate fc1.
    cudaEventRecord(ev_fork, 0);
    cudaStreamWaitEvent(s1, ev_fork, 0);

    // main stream (0): conversions feeding fc1
    f2h_kernel<<<T_TOK * D_DIM / 8 / 256, 256>>>((const float4*)x, (uint4*)xh_p);
    f2h_kernel<<<(size_t)E_EXP * 2 * H_DIM * D_DIM / 8 / 256, 256>>>
        ((const float4*)W1, (uint4*)w1h_p);

    // side stream: route (gates fc1), then fc2-only prep
    route_fused<<<1, 1024, 0, s1>>>(idx, w);
    cudaEventRecord(ev_route, s1);
    f2h_kernel<<<(size_t)E_EXP * D_DIM * H_DIM / 8 / 256, 256, 0, s1>>>
        ((const float4*)W2, (uint4*)w2h_p);
    int n4 = T_TOK * D_DIM / 4;
    zero_y_kernel<<<(n4 + 255) / 256, 256, 0, s1>>>((float4*)y, n4);
    cudaEventRecord(ev_join, s1);

    // fc1 needs route + x/W1 conversions
    cudaStreamWaitEvent(0, ev_route, 0);
    dim3 g1(NTILE_MAX, H_DIM / 64, 1);        // (72, 32)
    fc1_mma<<<g1, 256, SMEMSZ>>>();

    // fc2 needs fc1 + W2 conversion + zeroed y
    cudaStreamWaitEvent(0, ev_join, 0);
    dim3 g2(NTILE_MAX, D_DIM / 128, 2);       // (72, 8, 2)
    fc2_mma<<<g2, 256, SMEMSZ>>>(y);
}